// round 10
// baseline (speedup 1.0000x reference)
#include <cuda_runtime.h>
#include <math.h>

#define TT 512
#define BB 32
#define II 512
#define HH 1024
#define BH (BB*HH)
#define TBH (TT*BB*HH)
#define NBLK 128

__device__ float g_P[(size_t)4 * TBH];
__device__ float g_h[BH];
__device__ float g_c[2][BH];
__device__ float g_po[BH];
__device__ float g_bias[4][HH];
__device__ float g_Wpk[(size_t)448 * 16384];      // 384 phase1 tiles + 64 Wcyo tiles
__device__ float g_WpkI[(size_t)4 * 64 * 8192];   // input weights, frag-packed
__device__ __align__(16) unsigned g_fB[128];
__device__ __align__(16) unsigned g_fC[128];
__device__ volatile unsigned g_genB;
__device__ volatile unsigned g_genC;

__device__ __forceinline__ unsigned cvt_tf32(float x) {
    unsigned r; asm("cvt.rna.tf32.f32 %0, %1;" : "=r"(r) : "f"(x)); return r;
}
__device__ __forceinline__ void st4tf(float* p, float4 v) {
    uint4 u; u.x = cvt_tf32(v.x); u.y = cvt_tf32(v.y);
    u.z = cvt_tf32(v.z); u.w = cvt_tf32(v.w); *(uint4*)p = u;
}
__device__ __forceinline__ void mma_tf32(float* d, uint4 a, unsigned b0, unsigned b1) {
    asm("mma.sync.aligned.m16n8k8.row.col.f32.tf32.tf32.f32 "
        "{%0,%1,%2,%3},{%4,%5,%6,%7},{%8,%9},{%0,%1,%2,%3};"
        : "+f"(d[0]), "+f"(d[1]), "+f"(d[2]), "+f"(d[3])
        : "r"(a.x), "r"(a.y), "r"(a.z), "r"(a.w), "r"(b0), "r"(b1));
}

__device__ __forceinline__ void bar_arrive(unsigned* f, int bId, unsigned v) {
    __syncthreads();
    if (threadIdx.x == 0) {
        __threadfence();
        asm volatile("st.relaxed.gpu.global.u32 [%0], %1;"
                     :: "l"(f + bId), "r"(v) : "memory");
    }
}
__device__ __forceinline__ void bar_master(const unsigned* f, int n, unsigned v,
                                           volatile unsigned* gen) {
    if (threadIdx.x < 32) {
        int i = threadIdx.x * 4;
        bool act = i < n;
        const unsigned* p = f + i;
        for (;;) {
            unsigned x0 = v, x1 = v, x2 = v, x3 = v;
            if (act)
                asm volatile("ld.relaxed.gpu.global.v4.u32 {%0,%1,%2,%3},[%4];"
                             : "=r"(x0), "=r"(x1), "=r"(x2), "=r"(x3) : "l"(p));
            bool ok = (x0 >= v) && (x1 >= v) && (x2 >= v) && (x3 >= v);
            if (__all_sync(0xffffffffu, ok)) break;
        }
        __threadfence();
        if (threadIdx.x == 0) *gen = v;
    }
    __syncthreads();
}
__device__ __forceinline__ void bar_spin(volatile unsigned* gen, unsigned v) {
    if (threadIdx.x == 0) {
        while (*gen < v) { }
        __threadfence();
    }
    __syncthreads();
}

__global__ void __launch_bounds__(256) init_kernel(
    const float* __restrict__ h0, const float* __restrict__ c0,
    const float* __restrict__ b_ii, const float* __restrict__ b_hi,
    const float* __restrict__ b_ci, const float* __restrict__ b_if,
    const float* __restrict__ b_hf, const float* __restrict__ b_cf,
    const float* __restrict__ b_ic, const float* __restrict__ b_hc,
    const float* __restrict__ b_io, const float* __restrict__ b_ho,
    const float* __restrict__ b_cyo)
{
    int i = blockIdx.x * blockDim.x + threadIdx.x;
    if (i < BH) { g_h[i] = h0[i]; g_c[0][i] = c0[i]; }
    if (i < HH) {
        g_bias[0][i] = b_ii[i] + b_hi[i] + b_ci[i];
        g_bias[1][i] = b_if[i] + b_hf[i] + b_cf[i];
        g_bias[2][i] = b_ic[i] + b_hc[i];
        g_bias[3][i] = b_io[i] + b_ho[i] + b_cyo[i];
    }
    if (i < 128) { g_fB[i] = 0; g_fC[i] = 0; }
    if (i == 0) { g_genB = 0; g_genC = 0; }
}

// Pack weights into m16n8k8 A-fragment order (same layout as R8).
__global__ void __launch_bounds__(256) pack_kernel(
    const float* __restrict__ w0, const float* __restrict__ w1,
    const float* __restrict__ w2, const float* __restrict__ w3,
    const float* __restrict__ w4, const float* __restrict__ w5,
    const float* __restrict__ w6)
{
    int gid = blockIdx.x * 256 + threadIdx.x;
    int s = gid >> 14, rem = gid & 16383;
    int kt = rem >> 7, lane = (rem >> 2) & 31, jj = rem & 3;
    int kcol = kt * 8 + (lane & 3) + 4 * (jj >> 1);
    float v;
    if (s < 384) {
        int bId = s / 3, tt = s - 3 * bId;
        int r = (lane >> 2) + 8 * (jj & 1);
        int mat = tt * 2 + (r >> 3);
        int n = bId * 8 + (r & 7);
        const float* W = (mat == 0) ? w0 : (mat == 1) ? w1 : (mat == 2) ? w2 :
                         (mat == 3) ? w3 : (mat == 4) ? w4 : w5;
        v = __ldg(&W[n * HH + kcol]);
    } else {
        int ng = s - 384;
        int row = ng * 16 + (lane >> 2) + 8 * (jj & 1);
        v = __ldg(&w6[row * HH + kcol]);
    }
    g_Wpk[gid] = __uint_as_float(cvt_tf32(v));
}

__global__ void __launch_bounds__(256) pack_in_kernel(
    const float* __restrict__ w0, const float* __restrict__ w1,
    const float* __restrict__ w2, const float* __restrict__ w3)
{
    int gid = blockIdx.x * 256 + threadIdx.x;
    int mat = gid >> 19, rem = gid & 524287;
    int ng = rem >> 13, kt = (rem >> 7) & 63, lane = (rem >> 2) & 31, jj = rem & 3;
    int row = ng * 16 + (lane >> 2) + 8 * (jj & 1);
    int col = kt * 8 + (lane & 3) + 4 * (jj >> 1);
    const float* W = (mat == 0) ? w0 : (mat == 1) ? w1 : (mat == 2) ? w2 : w3;
    g_WpkI[gid] = __uint_as_float(cvt_tf32(__ldg(&W[row * II + col])));
}

// proj (tf32 mma): unchanged from R8
#define PROJ_SMEM (32768 + 2*2176 + 2176 + 64)
__global__ void __launch_bounds__(256) proj2_kernel(const float* __restrict__ X)
{
    extern __shared__ float smem[];
    float* sA = smem;
    float* sX = smem + 32768;
    float* sT = smem + 32768 + 4352;
    float* sBias = sT + 2176;

    const int tid = threadIdx.x;
    const int bn = blockIdx.x & 63, bm = blockIdx.x >> 6;
    const int w = tid >> 5, lane = tid & 31;
    const int ta = w >> 1, mh = w & 1;

    {
        const float4* src = (const float4*)(g_WpkI + (size_t)(bn * 4) * 8192);
        float4* dst = (float4*)sA;
        for (int p = tid; p < 8192; p += 256) dst[p] = __ldg(src + p);
    }
    if (tid < 64) {
        int np = bn * 64 + tid;
        sBias[tid] = g_bias[np >> 10][np & 1023];
    }

    const int v1 = tid + 256;
    const int b0s = tid >> 4, kq0 = (tid & 15) * 4;
    const int b1s = v1 >> 4,  kq1 = (v1 & 15) * 4;
    const int brow0 = (mh * 16 + (lane >> 2)) * 68 + (lane & 3);
    const int brow1 = (mh * 16 + 8 + (lane >> 2)) * 68 + (lane & 3);

    const float* tilebase = sA + ta * 8192;
    const int gate = (bn * 64) >> 10;
    const int nbase = (bn * 64) & 1023;
    __syncthreads();

    for (int mc = 0; mc < 256; mc++) {
        const int m0 = bm * 8192 + mc * 32;

        float acc[2][4];
#pragma unroll
        for (int g = 0; g < 2; g++)
#pragma unroll
            for (int j = 0; j < 4; j++) acc[g][j] = 0.f;

        float4 px0 = __ldg((const float4*)(X + (size_t)(m0 + b0s) * II + kq0));
        float4 px1 = __ldg((const float4*)(X + (size_t)(m0 + b1s) * II + kq1));

        for (int j = 0; j < 8; j++) {
            float* xb = sX + (j & 1) * 2176;
            __syncthreads();
            st4tf(xb + b0s * 68 + kq0, px0);
            st4tf(xb + b1s * 68 + kq1, px1);
            __syncthreads();
            if (j < 7) {
                int k1 = (j + 1) * 64;
                px0 = __ldg((const float4*)(X + (size_t)(m0 + b0s) * II + k1 + kq0));
                px1 = __ldg((const float4*)(X + (size_t)(m0 + b1s) * II + k1 + kq1));
            }
#pragma unroll
            for (int kt = 0; kt < 8; kt++) {
                const int colo = kt * 8;
                unsigned x0a = *(const unsigned*)(xb + brow0 + colo);
                unsigned x1a = *(const unsigned*)(xb + brow0 + colo + 4);
                unsigned x0b = *(const unsigned*)(xb + brow1 + colo);
                unsigned x1b = *(const unsigned*)(xb + brow1 + colo + 4);
                uint4 a = *(const uint4*)(tilebase + (j * 8 + kt) * 128 + lane * 4);
                mma_tf32(acc[0], a, x0a, x1a);
                mma_tf32(acc[1], a, x0b, x1b);
            }
        }

        __syncthreads();
#pragma unroll
        for (int g = 0; g < 2; g++)
#pragma unroll
            for (int j = 0; j < 4; j++) {
                int nrow = ta * 16 + (lane >> 2) + 8 * (j >> 1);
                int mcol = mh * 16 + g * 8 + 2 * (lane & 3) + (j & 1);
                sT[mcol * 68 + nrow] = acc[g][j];
            }
        __syncthreads();
#pragma unroll
        for (int e = 0; e < 2; e++) {
            int idx = tid + e * 256;
            int row = idx >> 4, q = idx & 15;
            float4 v = *(float4*)(sT + row * 68 + q * 4);
            v.x += sBias[q * 4 + 0]; v.y += sBias[q * 4 + 1];
            v.z += sBias[q * 4 + 2]; v.w += sBias[q * 4 + 3];
            *(float4*)(g_P + (size_t)gate * TBH + (size_t)(m0 + row) * HH + nbase + q * 4) = v;
        }
    }
}

// persistent tf32 recurrence: B operands loaded directly from L2 (no staging)
#define SMEM_FLOATS (49152 + 4608)
extern "C" __global__ void __launch_bounds__(256) lstm_kernel(float* __restrict__ out)
{
    extern __shared__ float smem[];
    float* sW = smem;               // 3 tiles x 16384
    float* sB = smem + 49152;       // reduction scratch (4608 floats)

    const int tid = threadIdx.x, bId = blockIdx.x;
    const int w = tid >> 5, lane = tid & 31;
    const int kw = w >> 1, bgset = w & 1;

    const int s0 = 3 * bId;
#pragma unroll
    for (int tt = 0; tt < 3; tt++) {
        const float4* src = (const float4*)(g_Wpk + (size_t)(s0 + tt) * 16384);
        float4* dst = (float4*)(sW + tt * 16384);
        for (int p = tid; p < 4096; p += 256) dst[p] = __ldg(src + p);
    }

    // B-fragment row bases (phase 1): batch rows br, br+8
    const int br = bgset * 16 + (lane >> 2);
    const int kb = lane & 3;

    // pointwise ownership (warps 0,1): col nl, 4 (g,jb) batch slots
    const int nl = lane >> 2;
    const int nown = bId * 8 + nl;
    int offs[4];
#pragma unroll
    for (int gj = 0; gj < 4; gj++) {
        int g = gj >> 1, jb = gj & 1;
        int bcol = bgset * 16 + g * 8 + 2 * (lane & 3) + jb;
        offs[gj] = bcol * HH + nown;
    }

    // phase-2 roles: tile ng, batch half; k-split 8 ways (16 ktiles/warp)
    const int half = bId >> 6, ng = bId & 63;
    const float* wsrc2 = g_Wpk + (size_t)(384 + ng) * 16384;
    const int pr = half * 16 + (lane >> 2);
    float* sRedW = sB;                     // 7*32*8 = 1792

    __syncthreads();

    // own-cy register carry (warps 0,1): init from c0
    float cyreg[4];
    if (w < 2) {
#pragma unroll
        for (int gj = 0; gj < 4; gj++) cyreg[gj] = __ldcg(&g_c[0][offs[gj]]);
    }

    for (int t = 0; t < TT; t++) {
        const int cur = t & 1, nxt = cur ^ 1;
        const float* c_in = g_c[cur];

        // prefetch pointwise P operands (warps 0,1)
        float pP[4][4];
        if (w < 2) {
#pragma unroll
            for (int gj = 0; gj < 4; gj++) {
                size_t pb = (size_t)t * BH + offs[gj];
                pP[0][gj] = __ldg(&g_P[pb]);
                pP[1][gj] = __ldg(&g_P[(size_t)TBH + pb]);
                pP[2][gj] = __ldg(&g_P[2 * (size_t)TBH + pb]);
                pP[3][gj] = __ldg(&g_P[3 * (size_t)TBH + pb]);
            }
        }

        // ---------- phase 1: direct-L2 B frags, SMEM A frags ----------
        float acc[3][2][4];
#pragma unroll
        for (int a = 0; a < 3; a++)
#pragma unroll
            for (int g = 0; g < 2; g++)
#pragma unroll
                for (int j = 0; j < 4; j++) acc[a][g][j] = 0.f;

        const float* hA = g_h + br * HH;
        const float* hBp = g_h + (br + 8) * HH;
        const float* cA = c_in + br * HH;
        const float* cBp = c_in + (br + 8) * HH;

#pragma unroll 4
        for (int u = 0; u < 32; u++) {
            const int k = kw * 256 + u * 8 + kb;
            float h0a = __ldcg(hA + k),  h1a = __ldcg(hA + k + 4);
            float h0b = __ldcg(hBp + k), h1b = __ldcg(hBp + k + 4);
            float c0a = __ldcg(cA + k),  c1a = __ldcg(cA + k + 4);
            float c0b = __ldcg(cBp + k), c1b = __ldcg(cBp + k + 4);
            unsigned uh0a = cvt_tf32(h0a), uh1a = cvt_tf32(h1a);
            unsigned uh0b = cvt_tf32(h0b), uh1b = cvt_tf32(h1b);
            unsigned uc0a = cvt_tf32(c0a), uc1a = cvt_tf32(c1a);
            unsigned uc0b = cvt_tf32(c0b), uc1b = cvt_tf32(c1b);
            const int gkt = kw * 32 + u;
            uint4 a0 = *(const uint4*)(sW + gkt * 128 + lane * 4);
            uint4 a1 = *(const uint4*)(sW + 16384 + gkt * 128 + lane * 4);
            uint4 a2 = *(const uint4*)(sW + 32768 + gkt * 128 + lane * 4);
            mma_tf32(acc[0][0], a0, uh0a, uh1a);
            mma_tf32(acc[0][1], a0, uh0b, uh1b);
            mma_tf32(acc[1][0], a1, uh0a, uh1a);
            mma_tf32(acc[1][1], a1, uh0b, uh1b);
            mma_tf32(acc[2][0], a2, uc0a, uc1a);
            mma_tf32(acc[2][1], a2, uc0b, uc1b);
        }

        // cross-k-split reduction; warps 0,1 (kw==0) hold totals
        __syncthreads();
        if (kw > 0) {
            float* dst = sB + (((kw - 1) * 2 + bgset) * 32 + lane) * 24;
#pragma unroll
            for (int a = 0; a < 3; a++)
#pragma unroll
                for (int g = 0; g < 2; g++)
#pragma unroll
                    for (int j = 0; j < 4; j++) dst[a * 8 + g * 4 + j] = acc[a][g][j];
        }
        __syncthreads();
        if (kw == 0) {
#pragma unroll
            for (int r = 0; r < 3; r++) {
                const float* sp = sB + ((r * 2 + bgset) * 32 + lane) * 24;
#pragma unroll
                for (int a = 0; a < 3; a++)
#pragma unroll
                    for (int g = 0; g < 2; g++)
#pragma unroll
                        for (int j = 0; j < 4; j++) acc[a][g][j] += sp[a * 8 + g * 4 + j];
            }
            // local pointwise: gates, cy, po
#pragma unroll
            for (int gj = 0; gj < 4; gj++) {
                int g = gj >> 1, jb = gj & 1;
                float hi = acc[0][g][jb],     hf = acc[0][g][2 + jb];
                float hc = acc[1][g][jb],     ho = acc[1][g][2 + jb];
                float ci = acc[2][g][jb],     cf = acc[2][g][2 + jb];
                float pi = pP[0][gj] + hi + ci;
                float pf = pP[1][gj] + hf + cf;
                float pg = pP[2][gj] + hc;
                float po = pP[3][gj] + ho;
                float iv = 1.f / (1.f + expf(-pi));
                float fv = 1.f / (1.f + expf(-pf));
                float gv = tanhf(pg);
                float cy = fmaf(fv, cyreg[gj], iv * gv);
                cyreg[gj] = cy;
                g_c[nxt][offs[gj]] = cy;
                g_po[offs[gj]] = po;
            }
        }
        // barrier B (cy/po published)
        bar_arrive(g_fB, bId, (unsigned)(t + 1));
        if (bId == 0) bar_master(g_fB, 128, (unsigned)(t + 1), &g_genB);
        else          bar_spin(&g_genB, (unsigned)(t + 1));

        // ---------- phase 2: o = sig(po + cy@Wcyo^T), h ----------
        {
            const float* cyp = g_c[nxt];

            // epilogue operand prefetch (warp 0)
            float ppo[2][4], pcy[2][4];
            if (w == 0) {
#pragma unroll
                for (int g = 0; g < 2; g++)
#pragma unroll
                    for (int j = 0; j < 4; j++) {
                        int row = ng * 16 + (lane >> 2) + 8 * (j >> 1);
                        int bcol = half * 16 + g * 8 + 2 * (lane & 3) + (j & 1);
                        int off = bcol * HH + row;
                        ppo[g][j] = __ldcg(&g_po[off]);
                        pcy[g][j] = __ldcg(&cyp[off]);
                    }
            }

            float acc2[2][4];
#pragma unroll
            for (int g = 0; g < 2; g++)
#pragma unroll
                for (int j = 0; j < 4; j++) acc2[g][j] = 0.f;

            const float* yA = cyp + pr * HH;
            const float* yB = cyp + (pr + 8) * HH;

#pragma unroll 4
            for (int u = 0; u < 16; u++) {
                const int kt = w * 16 + u;
                const int k = kt * 8 + kb;
                float y0a = __ldcg(yA + k), y1a = __ldcg(yA + k + 4);
                float y0b = __ldcg(yB + k), y1b = __ldcg(yB + k + 4);
                unsigned u0a = cvt_tf32(y0a), u1a = cvt_tf32(y1a);
                unsigned u0b = cvt_tf32(y0b), u1b = cvt_tf32(y1b);
                uint4 af = __ldg((const uint4*)(wsrc2 + kt * 128) + lane);
                mma_tf32(acc2[0], af, u0a, u1a);
                mma_tf32(acc2[1], af, u0b, u1b);
            }

            // reduce over 8 k-split warps
            __syncthreads();
            if (w > 0) {
                float* dst = sRedW + ((w - 1) * 32 + lane) * 8;
#pragma unroll
                for (int g = 0; g < 2; g++)
#pragma unroll
                    for (int j = 0; j < 4; j++) dst[g * 4 + j] = acc2[g][j];
            }
            __syncthreads();
            if (w == 0) {
#pragma unroll
                for (int r = 0; r < 7; r++) {
                    const float* sp = sRedW + (r * 32 + lane) * 8;
#pragma unroll
                    for (int g = 0; g < 2; g++)
#pragma unroll
                        for (int j = 0; j < 4; j++) acc2[g][j] += sp[g * 4 + j];
                }
#pragma unroll
                for (int g = 0; g < 2; g++)
#pragma unroll
                    for (int j = 0; j < 4; j++) {
                        int row = ng * 16 + (lane >> 2) + 8 * (j >> 1);
                        int bcol = half * 16 + g * 8 + 2 * (lane & 3) + (j & 1);
                        int off = bcol * HH + row;
                        float o = 1.f / (1.f + expf(-(ppo[g][j] + acc2[g][j])));
                        float hy = o * tanhf(pcy[g][j]);
                        g_h[off] = hy;
                        out[(size_t)t * BH + off] = hy;
                    }
            }
        }
        // barrier C (h published)
        bar_arrive(g_fC, bId, (unsigned)(t + 1));
        if (bId == 0) bar_master(g_fC, 128, (unsigned)(t + 1), &g_genC);
        else          bar_spin(&g_genC, (unsigned)(t + 1));
    }
}

extern "C" void kernel_launch(void* const* d_in, const int* in_sizes, int n_in,
                              void* d_out, int out_size)
{
    const float* X     = (const float*)d_in[0];
    const float* h0    = (const float*)d_in[1];
    const float* c0    = (const float*)d_in[2];
    const float* w_ii  = (const float*)d_in[3];
    const float* w_hi  = (const float*)d_in[4];
    const float* w_ci  = (const float*)d_in[5];
    const float* w_if  = (const float*)d_in[6];
    const float* w_hf  = (const float*)d_in[7];
    const float* w_cf  = (const float*)d_in[8];
    const float* w_ic  = (const float*)d_in[9];
    const float* w_hc  = (const float*)d_in[10];
    const float* w_io  = (const float*)d_in[11];
    const float* w_ho  = (const float*)d_in[12];
    const float* w_cyo = (const float*)d_in[13];
    float* out = (float*)d_out;

    cudaFuncSetAttribute(lstm_kernel,
                         cudaFuncAttributeMaxDynamicSharedMemorySize,
                         SMEM_FLOATS * 4);
    cudaFuncSetAttribute(proj2_kernel,
                         cudaFuncAttributeMaxDynamicSharedMemorySize,
                         PROJ_SMEM * 4);

    init_kernel<<<128, 256>>>(h0, c0,
        (const float*)d_in[14], (const float*)d_in[15], (const float*)d_in[16],
        (const float*)d_in[17], (const float*)d_in[18], (const float*)d_in[19],
        (const float*)d_in[20], (const float*)d_in[21], (const float*)d_in[22],
        (const float*)d_in[23], (const float*)d_in[24]);
    pack_kernel<<<28672, 256>>>(w_hi, w_hf, w_hc, w_ho, w_ci, w_cf, w_cyo);
    pack_in_kernel<<<8192, 256>>>(w_ii, w_if, w_ic, w_io);
    proj2_kernel<<<128, 256, PROJ_SMEM * 4>>>(X);
    lstm_kernel<<<NBLK, 256, SMEM_FLOATS * 4>>>(out);
}

// round 11
// speedup vs baseline: 1.0572x; 1.0572x over previous
#include <cuda_runtime.h>
#include <math.h>

#define TT 512
#define BB 32
#define II 512
#define HH 1024
#define BH (BB*HH)
#define TBH (TT*BB*HH)
#define NBLK 128

__device__ float g_P[(size_t)4 * TBH];
__device__ float g_htf[BH];               // tf32-rounded h (MMA operand)
__device__ float g_c[2][BH];              // exact cell state (pointwise/epilogue)
__device__ float g_ctf[2][BH];            // tf32-rounded cell state (MMA operand)
__device__ float g_po[BH];
__device__ float g_bias[4][HH];
__device__ float g_Wpk[(size_t)448 * 16384];
__device__ float g_WpkI[(size_t)4 * 64 * 8192];
__device__ __align__(16) unsigned g_fB[128];
__device__ __align__(16) unsigned g_fC[128];
__device__ volatile unsigned g_genB;
__device__ volatile unsigned g_genC;

__device__ __forceinline__ unsigned cvt_tf32(float x) {
    unsigned r; asm("cvt.rna.tf32.f32 %0, %1;" : "=r"(r) : "f"(x)); return r;
}
__device__ __forceinline__ void st4tf(float* p, float4 v) {
    uint4 u; u.x = cvt_tf32(v.x); u.y = cvt_tf32(v.y);
    u.z = cvt_tf32(v.z); u.w = cvt_tf32(v.w); *(uint4*)p = u;
}
__device__ __forceinline__ void mma_tf32(float* d, uint4 a, unsigned b0, unsigned b1) {
    asm("mma.sync.aligned.m16n8k8.row.col.f32.tf32.tf32.f32 "
        "{%0,%1,%2,%3},{%4,%5,%6,%7},{%8,%9},{%0,%1,%2,%3};"
        : "+f"(d[0]), "+f"(d[1]), "+f"(d[2]), "+f"(d[3])
        : "r"(a.x), "r"(a.y), "r"(a.z), "r"(a.w), "r"(b0), "r"(b1));
}

__device__ __forceinline__ void bar_arrive(unsigned* f, int bId, unsigned v) {
    __syncthreads();
    if (threadIdx.x == 0) {
        __threadfence();
        asm volatile("st.relaxed.gpu.global.u32 [%0], %1;"
                     :: "l"(f + bId), "r"(v) : "memory");
    }
}
__device__ __forceinline__ void bar_master(const unsigned* f, int n, unsigned v,
                                           volatile unsigned* gen) {
    if (threadIdx.x < 32) {
        int i = threadIdx.x * 4;
        bool act = i < n;
        const unsigned* p = f + i;
        for (;;) {
            unsigned x0 = v, x1 = v, x2 = v, x3 = v;
            if (act)
                asm volatile("ld.relaxed.gpu.global.v4.u32 {%0,%1,%2,%3},[%4];"
                             : "=r"(x0), "=r"(x1), "=r"(x2), "=r"(x3) : "l"(p));
            bool ok = (x0 >= v) && (x1 >= v) && (x2 >= v) && (x3 >= v);
            if (__all_sync(0xffffffffu, ok)) break;
        }
        __threadfence();
        if (threadIdx.x == 0) *gen = v;
    }
    __syncthreads();
}
__device__ __forceinline__ void bar_spin(volatile unsigned* gen, unsigned v) {
    if (threadIdx.x == 0) {
        while (*gen < v) { }
        __threadfence();
    }
    __syncthreads();
}

__global__ void __launch_bounds__(256) init_kernel(
    const float* __restrict__ h0, const float* __restrict__ c0,
    const float* __restrict__ b_ii, const float* __restrict__ b_hi,
    const float* __restrict__ b_ci, const float* __restrict__ b_if,
    const float* __restrict__ b_hf, const float* __restrict__ b_cf,
    const float* __restrict__ b_ic, const float* __restrict__ b_hc,
    const float* __restrict__ b_io, const float* __restrict__ b_ho,
    const float* __restrict__ b_cyo)
{
    int i = blockIdx.x * blockDim.x + threadIdx.x;
    if (i < BH) {
        float h = h0[i], c = c0[i];
        g_htf[i] = __uint_as_float(cvt_tf32(h));
        g_c[0][i] = c;
        g_ctf[0][i] = __uint_as_float(cvt_tf32(c));
    }
    if (i < HH) {
        g_bias[0][i] = b_ii[i] + b_hi[i] + b_ci[i];
        g_bias[1][i] = b_if[i] + b_hf[i] + b_cf[i];
        g_bias[2][i] = b_ic[i] + b_hc[i];
        g_bias[3][i] = b_io[i] + b_ho[i] + b_cyo[i];
    }
    if (i < 128) { g_fB[i] = 0; g_fC[i] = 0; }
    if (i == 0) { g_genB = 0; g_genC = 0; }
}

// Pack weights into m16n8k8 A-fragment order (layout as R8).
__global__ void __launch_bounds__(256) pack_kernel(
    const float* __restrict__ w0, const float* __restrict__ w1,
    const float* __restrict__ w2, const float* __restrict__ w3,
    const float* __restrict__ w4, const float* __restrict__ w5,
    const float* __restrict__ w6)
{
    int gid = blockIdx.x * 256 + threadIdx.x;
    int s = gid >> 14, rem = gid & 16383;
    int kt = rem >> 7, lane = (rem >> 2) & 31, jj = rem & 3;
    int kcol = kt * 8 + (lane & 3) + 4 * (jj >> 1);
    float v;
    if (s < 384) {
        int bId = s / 3, tt = s - 3 * bId;
        int r = (lane >> 2) + 8 * (jj & 1);
        int mat = tt * 2 + (r >> 3);
        int n = bId * 8 + (r & 7);
        const float* W = (mat == 0) ? w0 : (mat == 1) ? w1 : (mat == 2) ? w2 :
                         (mat == 3) ? w3 : (mat == 4) ? w4 : w5;
        v = __ldg(&W[n * HH + kcol]);
    } else {
        int ng = s - 384;
        int row = ng * 16 + (lane >> 2) + 8 * (jj & 1);
        v = __ldg(&w6[row * HH + kcol]);
    }
    g_Wpk[gid] = __uint_as_float(cvt_tf32(v));
}

__global__ void __launch_bounds__(256) pack_in_kernel(
    const float* __restrict__ w0, const float* __restrict__ w1,
    const float* __restrict__ w2, const float* __restrict__ w3)
{
    int gid = blockIdx.x * 256 + threadIdx.x;
    int mat = gid >> 19, rem = gid & 524287;
    int ng = rem >> 13, kt = (rem >> 7) & 63, lane = (rem >> 2) & 31, jj = rem & 3;
    int row = ng * 16 + (lane >> 2) + 8 * (jj & 1);
    int col = kt * 8 + (lane & 3) + 4 * (jj >> 1);
    const float* W = (mat == 0) ? w0 : (mat == 1) ? w1 : (mat == 2) ? w2 : w3;
    g_WpkI[gid] = __uint_as_float(cvt_tf32(__ldg(&W[row * II + col])));
}

// proj (tf32 mma): unchanged from R8
#define PROJ_SMEM (32768 + 2*2176 + 2176 + 64)
__global__ void __launch_bounds__(256) proj2_kernel(const float* __restrict__ X)
{
    extern __shared__ float smem[];
    float* sA = smem;
    float* sX = smem + 32768;
    float* sT = smem + 32768 + 4352;
    float* sBias = sT + 2176;

    const int tid = threadIdx.x;
    const int bn = blockIdx.x & 63, bm = blockIdx.x >> 6;
    const int w = tid >> 5, lane = tid & 31;
    const int ta = w >> 1, mh = w & 1;

    {
        const float4* src = (const float4*)(g_WpkI + (size_t)(bn * 4) * 8192);
        float4* dst = (float4*)sA;
        for (int p = tid; p < 8192; p += 256) dst[p] = __ldg(src + p);
    }
    if (tid < 64) {
        int np = bn * 64 + tid;
        sBias[tid] = g_bias[np >> 10][np & 1023];
    }

    const int v1 = tid + 256;
    const int b0s = tid >> 4, kq0 = (tid & 15) * 4;
    const int b1s = v1 >> 4,  kq1 = (v1 & 15) * 4;
    const int brow0 = (mh * 16 + (lane >> 2)) * 68 + (lane & 3);
    const int brow1 = (mh * 16 + 8 + (lane >> 2)) * 68 + (lane & 3);

    const float* tilebase = sA + ta * 8192;
    const int gate = (bn * 64) >> 10;
    const int nbase = (bn * 64) & 1023;
    __syncthreads();

    for (int mc = 0; mc < 256; mc++) {
        const int m0 = bm * 8192 + mc * 32;

        float acc[2][4];
#pragma unroll
        for (int g = 0; g < 2; g++)
#pragma unroll
            for (int j = 0; j < 4; j++) acc[g][j] = 0.f;

        float4 px0 = __ldg((const float4*)(X + (size_t)(m0 + b0s) * II + kq0));
        float4 px1 = __ldg((const float4*)(X + (size_t)(m0 + b1s) * II + kq1));

        for (int j = 0; j < 8; j++) {
            float* xb = sX + (j & 1) * 2176;
            __syncthreads();
            st4tf(xb + b0s * 68 + kq0, px0);
            st4tf(xb + b1s * 68 + kq1, px1);
            __syncthreads();
            if (j < 7) {
                int k1 = (j + 1) * 64;
                px0 = __ldg((const float4*)(X + (size_t)(m0 + b0s) * II + k1 + kq0));
                px1 = __ldg((const float4*)(X + (size_t)(m0 + b1s) * II + k1 + kq1));
            }
#pragma unroll
            for (int kt = 0; kt < 8; kt++) {
                const int colo = kt * 8;
                unsigned x0a = *(const unsigned*)(xb + brow0 + colo);
                unsigned x1a = *(const unsigned*)(xb + brow0 + colo + 4);
                unsigned x0b = *(const unsigned*)(xb + brow1 + colo);
                unsigned x1b = *(const unsigned*)(xb + brow1 + colo + 4);
                uint4 a = *(const uint4*)(tilebase + (j * 8 + kt) * 128 + lane * 4);
                mma_tf32(acc[0], a, x0a, x1a);
                mma_tf32(acc[1], a, x0b, x1b);
            }
        }

        __syncthreads();
#pragma unroll
        for (int g = 0; g < 2; g++)
#pragma unroll
            for (int j = 0; j < 4; j++) {
                int nrow = ta * 16 + (lane >> 2) + 8 * (j >> 1);
                int mcol = mh * 16 + g * 8 + 2 * (lane & 3) + (j & 1);
                sT[mcol * 68 + nrow] = acc[g][j];
            }
        __syncthreads();
#pragma unroll
        for (int e = 0; e < 2; e++) {
            int idx = tid + e * 256;
            int row = idx >> 4, q = idx & 15;
            float4 v = *(float4*)(sT + row * 68 + q * 4);
            v.x += sBias[q * 4 + 0]; v.y += sBias[q * 4 + 1];
            v.z += sBias[q * 4 + 2]; v.w += sBias[q * 4 + 3];
            *(float4*)(g_P + (size_t)gate * TBH + (size_t)(m0 + row) * HH + nbase + q * 4) = v;
        }
    }
}

// persistent tf32 recurrence (R8 structure, optimized staging)
#define SMEM_FLOATS (49152 + 8704)
extern "C" __global__ void __launch_bounds__(256) lstm_kernel(float* __restrict__ out)
{
    extern __shared__ float smem[];
    float* sW  = smem;              // 3 tiles x 16384
    float* sB  = smem + 49152;      // staging + reduction
    float* sBh = sB;                // phase1: 2 x 2176 (h)
    float* sBc = sB + 2 * 2176;     // phase1: 2 x 2176 (c)

    const int tid = threadIdx.x, bId = blockIdx.x;
    const int w = tid >> 5, lane = tid & 31;
    const int kw = w >> 1, bgset = w & 1;

    const int s0 = 3 * bId;
#pragma unroll
    for (int tt = 0; tt < 3; tt++) {
        const float4* src = (const float4*)(g_Wpk + (size_t)(s0 + tt) * 16384);
        float4* dst = (float4*)(sW + tt * 16384);
        for (int p = tid; p < 4096; p += 256) dst[p] = __ldg(src + p);
    }

    const int v1 = tid + 256;
    const int b0s = tid >> 4, kq0 = (tid & 15) * 4;
    const int b1s = v1 >> 4,  kq1 = (v1 & 15) * 4;
    const int brow0 = (bgset * 16 + (lane >> 2)) * 68 + (lane & 3);
    const int brow1 = brow0 + 8 * 68;

    // pointwise ownership (warps 0,1)
    const int nl = lane >> 2;
    const int nown = bId * 8 + nl;
    int offs[4];
#pragma unroll
    for (int gj = 0; gj < 4; gj++) {
        int g = gj >> 1, jb = gj & 1;
        int bcol = bgset * 16 + g * 8 + 2 * (lane & 3) + jb;
        offs[gj] = bcol * HH + nown;
    }

    // phase-2 roles
    const int half = bId >> 6, ng = bId & 63;
    const float* wsrc2 = g_Wpk + (size_t)(384 + ng) * 16384;
    const int srow = tid >> 4, sq = (tid & 15) * 4;   // cy staging (16 rows)
    const int kb = lane & 3;
    const int prow0 = (lane >> 2) * 68 + kb;
    const int prow1 = prow0 + 8 * 68;
    float* sCy = sB;                  // 2 x 1088
    float* sRedW = sB + 4352;         // 1792

    __syncthreads();

    // own-cy register carry (warps 0,1): exact c0
    float cyreg[4];
    if (w < 2) {
#pragma unroll
        for (int gj = 0; gj < 4; gj++) cyreg[gj] = __ldcg(&g_c[0][offs[gj]]);
    }

    for (int t = 0; t < TT; t++) {
        const int cur = t & 1, nxt = cur ^ 1;
        const float* ctf_in = g_ctf[cur];

        // prefetch pointwise P operands (warps 0,1)
        float pP[4][4];
        if (w < 2) {
#pragma unroll
            for (int gj = 0; gj < 4; gj++) {
                size_t pb = (size_t)t * BH + offs[gj];
                pP[0][gj] = __ldg(&g_P[pb]);
                pP[1][gj] = __ldg(&g_P[(size_t)TBH + pb]);
                pP[2][gj] = __ldg(&g_P[2 * (size_t)TBH + pb]);
                pP[3][gj] = __ldg(&g_P[3 * (size_t)TBH + pb]);
            }
        }

        // ---------- phase 1: depth-3 prefetch, raw copies ----------
        float acc[3][2][4];
#pragma unroll
        for (int a = 0; a < 3; a++)
#pragma unroll
            for (int g = 0; g < 2; g++)
#pragma unroll
                for (int j = 0; j < 4; j++) acc[a][g][j] = 0.f;

        {   // chunk 0 direct to buf0
            float4 t0 = __ldcg((const float4*)(g_htf + b0s * HH + kq0));
            float4 t1 = __ldcg((const float4*)(g_htf + b1s * HH + kq1));
            float4 t2 = __ldcg((const float4*)(ctf_in + b0s * HH + kq0));
            float4 t3 = __ldcg((const float4*)(ctf_in + b1s * HH + kq1));
            *(float4*)(sBh + b0s * 68 + kq0) = t0;
            *(float4*)(sBh + b1s * 68 + kq1) = t1;
            *(float4*)(sBc + b0s * 68 + kq0) = t2;
            *(float4*)(sBc + b1s * 68 + kq1) = t3;
        }
        float4 rh[2][2], rc[2][2];
#pragma unroll
        for (int s = 0; s < 2; s++) {
            int k = (1 + s) * 64;
            rh[s][0] = __ldcg((const float4*)(g_htf + b0s * HH + k + kq0));
            rh[s][1] = __ldcg((const float4*)(g_htf + b1s * HH + k + kq1));
            rc[s][0] = __ldcg((const float4*)(ctf_in + b0s * HH + k + kq0));
            rc[s][1] = __ldcg((const float4*)(ctf_in + b1s * HH + k + kq1));
        }
        __syncthreads();

        for (int j = 0; j < 16; j++) {
            float* bh = sBh + (j & 1) * 2176;
            float* bc = sBc + (j & 1) * 2176;
            if (j < 15) {
                int s = j & 1;
                float* bhn = sBh + ((j + 1) & 1) * 2176;
                float* bcn = sBc + ((j + 1) & 1) * 2176;
                *(float4*)(bhn + b0s * 68 + kq0) = rh[s][0];
                *(float4*)(bhn + b1s * 68 + kq1) = rh[s][1];
                *(float4*)(bcn + b0s * 68 + kq0) = rc[s][0];
                *(float4*)(bcn + b1s * 68 + kq1) = rc[s][1];
                if (j < 13) {
                    int k3 = (j + 3) * 64;
                    rh[s][0] = __ldcg((const float4*)(g_htf + b0s * HH + k3 + kq0));
                    rh[s][1] = __ldcg((const float4*)(g_htf + b1s * HH + k3 + kq1));
                    rc[s][0] = __ldcg((const float4*)(ctf_in + b0s * HH + k3 + kq0));
                    rc[s][1] = __ldcg((const float4*)(ctf_in + b1s * HH + k3 + kq1));
                }
            }
#pragma unroll
            for (int q = 0; q < 2; q++) {
                const int kt = kw * 2 + q, colo = kt * 8;
                unsigned h0a = *(const unsigned*)(bh + brow0 + colo);
                unsigned h1a = *(const unsigned*)(bh + brow0 + colo + 4);
                unsigned h0b = *(const unsigned*)(bh + brow1 + colo);
                unsigned h1b = *(const unsigned*)(bh + brow1 + colo + 4);
                unsigned c0a = *(const unsigned*)(bc + brow0 + colo);
                unsigned c1a = *(const unsigned*)(bc + brow0 + colo + 4);
                unsigned c0b = *(const unsigned*)(bc + brow1 + colo);
                unsigned c1b = *(const unsigned*)(bc + brow1 + colo + 4);
                const int gkt = j * 8 + kt;
                uint4 a0 = *(const uint4*)(sW + gkt * 128 + lane * 4);
                uint4 a1 = *(const uint4*)(sW + 16384 + gkt * 128 + lane * 4);
                uint4 a2 = *(const uint4*)(sW + 32768 + gkt * 128 + lane * 4);
                mma_tf32(acc[0][0], a0, h0a, h1a);
                mma_tf32(acc[0][1], a0, h0b, h1b);
                mma_tf32(acc[1][0], a1, h0a, h1a);
                mma_tf32(acc[1][1], a1, h0b, h1b);
                mma_tf32(acc[2][0], a2, c0a, c1a);
                mma_tf32(acc[2][1], a2, c0b, c1b);
            }
            __syncthreads();
        }

        // cross-k-split reduction; warps 0,1 hold totals
        if (kw > 0) {
            float* dst = sB + (((kw - 1) * 2 + bgset) * 32 + lane) * 24;
#pragma unroll
            for (int a = 0; a < 3; a++)
#pragma unroll
                for (int g = 0; g < 2; g++)
#pragma unroll
                    for (int j = 0; j < 4; j++) dst[a * 8 + g * 4 + j] = acc[a][g][j];
        }
        __syncthreads();
        if (kw == 0) {
#pragma unroll
            for (int r = 0; r < 3; r++) {
                const float* sp = sB + ((r * 2 + bgset) * 32 + lane) * 24;
#pragma unroll
                for (int a = 0; a < 3; a++)
#pragma unroll
                    for (int g = 0; g < 2; g++)
#pragma unroll
                        for (int j = 0; j < 4; j++) acc[a][g][j] += sp[a * 8 + g * 4 + j];
            }
            // local pointwise: gates, cy, po
#pragma unroll
            for (int gj = 0; gj < 4; gj++) {
                int g = gj >> 1, jb = gj & 1;
                float hi = acc[0][g][jb],     hf = acc[0][g][2 + jb];
                float hc = acc[1][g][jb],     ho = acc[1][g][2 + jb];
                float ci = acc[2][g][jb],     cf = acc[2][g][2 + jb];
                float pi = pP[0][gj] + hi + ci;
                float pf = pP[1][gj] + hf + cf;
                float pg = pP[2][gj] + hc;
                float po = pP[3][gj] + ho;
                float iv = 1.f / (1.f + expf(-pi));
                float fv = 1.f / (1.f + expf(-pf));
                float gv = tanhf(pg);
                float cy = fmaf(fv, cyreg[gj], iv * gv);
                cyreg[gj] = cy;
                g_c[nxt][offs[gj]] = cy;
                g_ctf[nxt][offs[gj]] = __uint_as_float(cvt_tf32(cy));
                g_po[offs[gj]] = po;
            }
        }
        // barrier B (cy/po published)
        bar_arrive(g_fB, bId, (unsigned)(t + 1));
        if (bId == 0) bar_master(g_fB, 128, (unsigned)(t + 1), &g_genB);
        else          bar_spin(&g_genB, (unsigned)(t + 1));

        // ---------- phase 2: o = sig(po + cy@Wcyo^T), h ----------
        {
            const float* ctf_nx = g_ctf[nxt];
            const float* cyrow = ctf_nx + (half * 16 + srow) * HH;

            // epilogue operand prefetch (warp 0)
            float ppo[2][4], pcy[2][4];
            if (w == 0) {
#pragma unroll
                for (int g = 0; g < 2; g++)
#pragma unroll
                    for (int j = 0; j < 4; j++) {
                        int row = ng * 16 + (lane >> 2) + 8 * (j >> 1);
                        int bcol = half * 16 + g * 8 + 2 * (lane & 3) + (j & 1);
                        int off = bcol * HH + row;
                        ppo[g][j] = __ldcg(&g_po[off]);
                        pcy[g][j] = __ldcg(&g_c[nxt][off]);
                    }
            }

            float acc2[2][4];
#pragma unroll
            for (int g = 0; g < 2; g++)
#pragma unroll
                for (int j = 0; j < 4; j++) acc2[g][j] = 0.f;

            // prologue: chunk 0 direct; ry depth-3; A-frag ring depth-4
            *(float4*)(sCy + srow * 68 + sq) = __ldcg((const float4*)(cyrow + sq));
            float4 ry[2];
            ry[0] = __ldcg((const float4*)(cyrow + 64 + sq));
            ry[1] = __ldcg((const float4*)(cyrow + 128 + sq));
            uint4 ra[4];
#pragma unroll
            for (int s = 0; s < 4; s++)
                ra[s] = __ldg((const uint4*)(wsrc2 + (s * 8 + w) * 128) + lane);
            __syncthreads();

#pragma unroll
            for (int j = 0; j < 16; j++) {
                float* cb = sCy + (j & 1) * 1088;
                if (j < 15) {
                    *(float4*)(sCy + ((j + 1) & 1) * 1088 + srow * 68 + sq) = ry[j & 1];
                    if (j < 13)
                        ry[j & 1] = __ldcg((const float4*)(cyrow + (j + 3) * 64 + sq));
                }
                uint4 af = ra[j & 3];
                if (j < 12)
                    ra[j & 3] = __ldg((const uint4*)(wsrc2 + ((j + 4) * 8 + w) * 128) + lane);
                const int colo = w * 8;
                unsigned y0a = *(const unsigned*)(cb + prow0 + colo);
                unsigned y1a = *(const unsigned*)(cb + prow0 + colo + 4);
                unsigned y0b = *(const unsigned*)(cb + prow1 + colo);
                unsigned y1b = *(const unsigned*)(cb + prow1 + colo + 4);
                mma_tf32(acc2[0], af, y0a, y1a);
                mma_tf32(acc2[1], af, y0b, y1b);
                __syncthreads();
            }

            // reduce over 8 k-split warps
            if (w > 0) {
                float* dst = sRedW + ((w - 1) * 32 + lane) * 8;
#pragma unroll
                for (int g = 0; g < 2; g++)
#pragma unroll
                    for (int j = 0; j < 4; j++) dst[g * 4 + j] = acc2[g][j];
            }
            __syncthreads();
            if (w == 0) {
#pragma unroll
                for (int r = 0; r < 7; r++) {
                    const float* sp = sRedW + (r * 32 + lane) * 8;
#pragma unroll
                    for (int g = 0; g < 2; g++)
#pragma unroll
                        for (int j = 0; j < 4; j++) acc2[g][j] += sp[g * 4 + j];
                }
#pragma unroll
                for (int g = 0; g < 2; g++)
#pragma unroll
                    for (int j = 0; j < 4; j++) {
                        int row = ng * 16 + (lane >> 2) + 8 * (j >> 1);
                        int bcol = half * 16 + g * 8 + 2 * (lane & 3) + (j & 1);
                        int off = bcol * HH + row;
                        float o = 1.f / (1.f + expf(-(ppo[g][j] + acc2[g][j])));
                        float hy = o * tanhf(pcy[g][j]);
                        g_htf[off] = __uint_as_float(cvt_tf32(hy));
                        out[(size_t)t * BH + off] = hy;
                    }
            }
        }
        // barrier C (h published)
        bar_arrive(g_fC, bId, (unsigned)(t + 1));
        if (bId == 0) bar_master(g_fC, 128, (unsigned)(t + 1), &g_genC);
        else          bar_spin(&g_genC, (unsigned)(t + 1));
    }
}

extern "C" void kernel_launch(void* const* d_in, const int* in_sizes, int n_in,
                              void* d_out, int out_size)
{
    const float* X     = (const float*)d_in[0];
    const float* h0    = (const float*)d_in[1];
    const float* c0    = (const float*)d_in[2];
    const float* w_ii  = (const float*)d_in[3];
    const float* w_hi  = (const float*)d_in[4];
    const float* w_ci  = (const float*)d_in[5];
    const float* w_if  = (const float*)d_in[6];
    const float* w_hf  = (const float*)d_in[7];
    const float* w_cf  = (const float*)d_in[8];
    const float* w_ic  = (const float*)d_in[9];
    const float* w_hc  = (const float*)d_in[10];
    const float* w_io  = (const float*)d_in[11];
    const float* w_ho  = (const float*)d_in[12];
    const float* w_cyo = (const float*)d_in[13];
    float* out = (float*)d_out;

    cudaFuncSetAttribute(lstm_kernel,
                         cudaFuncAttributeMaxDynamicSharedMemorySize,
                         SMEM_FLOATS * 4);
    cudaFuncSetAttribute(proj2_kernel,
                         cudaFuncAttributeMaxDynamicSharedMemorySize,
                         PROJ_SMEM * 4);

    init_kernel<<<128, 256>>>(h0, c0,
        (const float*)d_in[14], (const float*)d_in[15], (const float*)d_in[16],
        (const float*)d_in[17], (const float*)d_in[18], (const float*)d_in[19],
        (const float*)d_in[20], (const float*)d_in[21], (const float*)d_in[22],
        (const float*)d_in[23], (const float*)d_in[24]);
    pack_kernel<<<28672, 256>>>(w_hi, w_hf, w_hc, w_ho, w_ci, w_cf, w_cyo);
    pack_in_kernel<<<8192, 256>>>(w_ii, w_if, w_ic, w_io);
    proj2_kernel<<<128, 256, PROJ_SMEM * 4>>>(X);
    lstm_kernel<<<NBLK, 256, SMEM_FLOATS * 4>>>(out);
}

// round 13
// speedup vs baseline: 1.4237x; 1.3467x over previous
#include <cuda_runtime.h>
#include <math.h>

#define TT 512
#define BB 32
#define II 512
#define HH 1024
#define BH (BB*HH)
#define TBH (TT*BB*HH)
#define NBLK 128

__device__ float g_P[(size_t)4 * TBH];
__device__ float g_htf[BH];               // tf32-rounded h (MMA operand)
__device__ float g_c[2][BH];              // exact cell state (pointwise/epilogue)
__device__ float g_ctf[2][BH];            // tf32-rounded cell state (MMA operand)
__device__ float g_po[BH];
__device__ float g_bias[4][HH];
__device__ float g_Wpk[(size_t)448 * 16384];      // 384 phase1 tiles + 64 Wcyo tiles
__device__ float g_WpkI[(size_t)4 * 64 * 8192];   // input weights, frag-packed
__device__ __align__(16) unsigned g_fB[128];
__device__ __align__(16) unsigned g_fC[128];
__device__ volatile unsigned g_genB;
__device__ volatile unsigned g_genC;

__device__ __forceinline__ unsigned cvt_tf32(float x) {
    unsigned r; asm("cvt.rna.tf32.f32 %0, %1;" : "=r"(r) : "f"(x)); return r;
}
__device__ __forceinline__ void st4tf(float* p, float4 v) {
    uint4 u; u.x = cvt_tf32(v.x); u.y = cvt_tf32(v.y);
    u.z = cvt_tf32(v.z); u.w = cvt_tf32(v.w); *(uint4*)p = u;
}
__device__ __forceinline__ void mma_tf32(float* d, uint4 a, unsigned b0, unsigned b1) {
    asm("mma.sync.aligned.m16n8k8.row.col.f32.tf32.tf32.f32 "
        "{%0,%1,%2,%3},{%4,%5,%6,%7},{%8,%9},{%0,%1,%2,%3};"
        : "+f"(d[0]), "+f"(d[1]), "+f"(d[2]), "+f"(d[3])
        : "r"(a.x), "r"(a.y), "r"(a.z), "r"(a.w), "r"(b0), "r"(b1));
}

__device__ __forceinline__ void bar_arrive(unsigned* f, int bId, unsigned v) {
    __syncthreads();
    if (threadIdx.x == 0) {
        __threadfence();
        asm volatile("st.relaxed.gpu.global.u32 [%0], %1;"
                     :: "l"(f + bId), "r"(v) : "memory");
    }
}
__device__ __forceinline__ void bar_master(const unsigned* f, int n, unsigned v,
                                           volatile unsigned* gen) {
    if (threadIdx.x < 32) {
        int i = threadIdx.x * 4;
        bool act = i < n;
        const unsigned* p = f + i;
        for (;;) {
            unsigned x0 = v, x1 = v, x2 = v, x3 = v;
            if (act)
                asm volatile("ld.relaxed.gpu.global.v4.u32 {%0,%1,%2,%3},[%4];"
                             : "=r"(x0), "=r"(x1), "=r"(x2), "=r"(x3) : "l"(p));
            bool ok = (x0 >= v) && (x1 >= v) && (x2 >= v) && (x3 >= v);
            if (__all_sync(0xffffffffu, ok)) break;
        }
        __threadfence();
        if (threadIdx.x == 0) *gen = v;
    }
    __syncthreads();
}
__device__ __forceinline__ void bar_spin(volatile unsigned* gen, unsigned v) {
    if (threadIdx.x == 0) {
        while (*gen < v) { }
        __threadfence();
    }
    __syncthreads();
}

__global__ void __launch_bounds__(256) init_kernel(
    const float* __restrict__ h0, const float* __restrict__ c0,
    const float* __restrict__ b_ii, const float* __restrict__ b_hi,
    const float* __restrict__ b_ci, const float* __restrict__ b_if,
    const float* __restrict__ b_hf, const float* __restrict__ b_cf,
    const float* __restrict__ b_ic, const float* __restrict__ b_hc,
    const float* __restrict__ b_io, const float* __restrict__ b_ho,
    const float* __restrict__ b_cyo)
{
    int i = blockIdx.x * blockDim.x + threadIdx.x;
    if (i < BH) {
        float h = h0[i], c = c0[i];
        g_htf[i] = __uint_as_float(cvt_tf32(h));
        g_c[0][i] = c;
        g_ctf[0][i] = __uint_as_float(cvt_tf32(c));
    }
    if (i < HH) {
        g_bias[0][i] = b_ii[i] + b_hi[i] + b_ci[i];
        g_bias[1][i] = b_if[i] + b_hf[i] + b_cf[i];
        g_bias[2][i] = b_ic[i] + b_hc[i];
        g_bias[3][i] = b_io[i] + b_ho[i] + b_cyo[i];
    }
    if (i < 128) { g_fB[i] = 0; g_fC[i] = 0; }
    if (i == 0) { g_genB = 0; g_genC = 0; }
}

// Pack weights into m16n8k8 A-fragment order (layout as R8).
__global__ void __launch_bounds__(256) pack_kernel(
    const float* __restrict__ w0, const float* __restrict__ w1,
    const float* __restrict__ w2, const float* __restrict__ w3,
    const float* __restrict__ w4, const float* __restrict__ w5,
    const float* __restrict__ w6)
{
    int gid = blockIdx.x * 256 + threadIdx.x;
    int s = gid >> 14, rem = gid & 16383;
    int kt = rem >> 7, lane = (rem >> 2) & 31, jj = rem & 3;
    int kcol = kt * 8 + (lane & 3) + 4 * (jj >> 1);
    float v;
    if (s < 384) {
        int bId = s / 3, tt = s - 3 * bId;
        int r = (lane >> 2) + 8 * (jj & 1);
        int mat = tt * 2 + (r >> 3);
        int n = bId * 8 + (r & 7);
        const float* W = (mat == 0) ? w0 : (mat == 1) ? w1 : (mat == 2) ? w2 :
                         (mat == 3) ? w3 : (mat == 4) ? w4 : w5;
        v = __ldg(&W[n * HH + kcol]);
    } else {
        int ng = s - 384;
        int row = ng * 16 + (lane >> 2) + 8 * (jj & 1);
        v = __ldg(&w6[row * HH + kcol]);
    }
    g_Wpk[gid] = __uint_as_float(cvt_tf32(v));
}

__global__ void __launch_bounds__(256) pack_in_kernel(
    const float* __restrict__ w0, const float* __restrict__ w1,
    const float* __restrict__ w2, const float* __restrict__ w3)
{
    int gid = blockIdx.x * 256 + threadIdx.x;
    int mat = gid >> 19, rem = gid & 524287;
    int ng = rem >> 13, kt = (rem >> 7) & 63, lane = (rem >> 2) & 31, jj = rem & 3;
    int row = ng * 16 + (lane >> 2) + 8 * (jj & 1);
    int col = kt * 8 + (lane & 3) + 4 * (jj >> 1);
    const float* W = (mat == 0) ? w0 : (mat == 1) ? w1 : (mat == 2) ? w2 : w3;
    g_WpkI[gid] = __uint_as_float(cvt_tf32(__ldg(&W[row * II + col])));
}

// proj (tf32 mma): unchanged from R8
#define PROJ_SMEM (32768 + 2*2176 + 2176 + 64)
__global__ void __launch_bounds__(256) proj2_kernel(const float* __restrict__ X)
{
    extern __shared__ float smem[];
    float* sA = smem;
    float* sX = smem + 32768;
    float* sT = smem + 32768 + 4352;
    float* sBias = sT + 2176;

    const int tid = threadIdx.x;
    const int bn = blockIdx.x & 63, bm = blockIdx.x >> 6;
    const int w = tid >> 5, lane = tid & 31;
    const int ta = w >> 1, mh = w & 1;

    {
        const float4* src = (const float4*)(g_WpkI + (size_t)(bn * 4) * 8192);
        float4* dst = (float4*)sA;
        for (int p = tid; p < 8192; p += 256) dst[p] = __ldg(src + p);
    }
    if (tid < 64) {
        int np = bn * 64 + tid;
        sBias[tid] = g_bias[np >> 10][np & 1023];
    }

    const int v1 = tid + 256;
    const int b0s = tid >> 4, kq0 = (tid & 15) * 4;
    const int b1s = v1 >> 4,  kq1 = (v1 & 15) * 4;
    const int brow0 = (mh * 16 + (lane >> 2)) * 68 + (lane & 3);
    const int brow1 = (mh * 16 + 8 + (lane >> 2)) * 68 + (lane & 3);

    const float* tilebase = sA + ta * 8192;
    const int gate = (bn * 64) >> 10;
    const int nbase = (bn * 64) & 1023;
    __syncthreads();

    for (int mc = 0; mc < 256; mc++) {
        const int m0 = bm * 8192 + mc * 32;

        float acc[2][4];
#pragma unroll
        for (int g = 0; g < 2; g++)
#pragma unroll
            for (int j = 0; j < 4; j++) acc[g][j] = 0.f;

        float4 px0 = __ldg((const float4*)(X + (size_t)(m0 + b0s) * II + kq0));
        float4 px1 = __ldg((const float4*)(X + (size_t)(m0 + b1s) * II + kq1));

        for (int j = 0; j < 8; j++) {
            float* xb = sX + (j & 1) * 2176;
            __syncthreads();
            st4tf(xb + b0s * 68 + kq0, px0);
            st4tf(xb + b1s * 68 + kq1, px1);
            __syncthreads();
            if (j < 7) {
                int k1 = (j + 1) * 64;
                px0 = __ldg((const float4*)(X + (size_t)(m0 + b0s) * II + k1 + kq0));
                px1 = __ldg((const float4*)(X + (size_t)(m0 + b1s) * II + k1 + kq1));
            }
#pragma unroll
            for (int kt = 0; kt < 8; kt++) {
                const int colo = kt * 8;
                unsigned x0a = *(const unsigned*)(xb + brow0 + colo);
                unsigned x1a = *(const unsigned*)(xb + brow0 + colo + 4);
                unsigned x0b = *(const unsigned*)(xb + brow1 + colo);
                unsigned x1b = *(const unsigned*)(xb + brow1 + colo + 4);
                uint4 a = *(const uint4*)(tilebase + (j * 8 + kt) * 128 + lane * 4);
                mma_tf32(acc[0], a, x0a, x1a);
                mma_tf32(acc[1], a, x0b, x1b);
            }
        }

        __syncthreads();
#pragma unroll
        for (int g = 0; g < 2; g++)
#pragma unroll
            for (int j = 0; j < 4; j++) {
                int nrow = ta * 16 + (lane >> 2) + 8 * (j >> 1);
                int mcol = mh * 16 + g * 8 + 2 * (lane & 3) + (j & 1);
                sT[mcol * 68 + nrow] = acc[g][j];
            }
        __syncthreads();
#pragma unroll
        for (int e = 0; e < 2; e++) {
            int idx = tid + e * 256;
            int row = idx >> 4, q = idx & 15;
            float4 v = *(float4*)(sT + row * 68 + q * 4);
            v.x += sBias[q * 4 + 0]; v.y += sBias[q * 4 + 1];
            v.z += sBias[q * 4 + 2]; v.w += sBias[q * 4 + 3];
            *(float4*)(g_P + (size_t)gate * TBH + (size_t)(m0 + row) * HH + nbase + q * 4) = v;
        }
    }
}

// persistent tf32 recurrence (R8 structure; prepacked tf32 state, reg A-frags)
#define SMEM_FLOATS (49152 + 8704)
extern "C" __global__ void __launch_bounds__(256) lstm_kernel(float* __restrict__ out)
{
    extern __shared__ float smem[];
    float* sW  = smem;              // 3 tiles x 16384
    float* sB  = smem + 49152;      // staging + reduction (8704)
    float* sBh = sB;                // phase1: 2 x 2176 (h)
    float* sBc = sB + 2 * 2176;     // phase1: 2 x 2176 (c)

    const int tid = threadIdx.x, bId = blockIdx.x;
    const int w = tid >> 5, lane = tid & 31;
    const int kw = w >> 1, bgset = w & 1;

    const int s0 = 3 * bId;
#pragma unroll
    for (int tt = 0; tt < 3; tt++) {
        const float4* src = (const float4*)(g_Wpk + (size_t)(s0 + tt) * 16384);
        float4* dst = (float4*)(sW + tt * 16384);
        for (int p = tid; p < 4096; p += 256) dst[p] = __ldg(src + p);
    }

    const int v1 = tid + 256;
    const int b0s = tid >> 4, kq0 = (tid & 15) * 4;
    const int b1s = v1 >> 4,  kq1 = (v1 & 15) * 4;
    const int brow0 = (bgset * 16 + (lane >> 2)) * 68 + (lane & 3);
    const int brow1 = brow0 + 8 * 68;

    // pointwise ownership (warps 0,1): col nl, 4 (g,jb) batch slots
    const int nl = lane >> 2;
    const int nown = bId * 8 + nl;
    int offs[4];
#pragma unroll
    for (int gj = 0; gj < 4; gj++) {
        int g = gj >> 1, jb = gj & 1;
        int bcol = bgset * 16 + g * 8 + 2 * (lane & 3) + jb;
        offs[gj] = bcol * HH + nown;
    }

    // phase-2 roles: tile ng, batch half; k-split 8 ways
    const int half = bId >> 6, ng = bId & 63;
    const float* wsrc2 = g_Wpk + (size_t)(384 + ng) * 16384;
    const int crow = tid >> 4, cq = (tid & 15) * 4;     // cy staging (16 rows)
    const int prow0 = (lane >> 2) * 68 + (lane & 3);
    const int prow1 = prow0 + 8 * 68;
    float* sCy = sB;                 // 2 bufs x 1088
    float* sRedW = sB + 4352;        // 1792

    __syncthreads();

    for (int t = 0; t < TT; t++) {
        const int cur = t & 1, nxt = cur ^ 1;
        const float* c_in  = g_c[cur];
        const float* ctf_in = g_ctf[cur];

        // prefetch pointwise operands (warps 0,1)
        float pP[4][4], pC[4];
        if (w < 2) {
#pragma unroll
            for (int gj = 0; gj < 4; gj++) {
                size_t pb = (size_t)t * BH + offs[gj];
                pP[0][gj] = __ldg(&g_P[pb]);
                pP[1][gj] = __ldg(&g_P[(size_t)TBH + pb]);
                pP[2][gj] = __ldg(&g_P[2 * (size_t)TBH + pb]);
                pP[3][gj] = __ldg(&g_P[3 * (size_t)TBH + pb]);
                pC[gj] = __ldcg(&c_in[offs[gj]]);
            }
        }

        // ---------- phase 1 ----------
        float acc[3][2][4];
#pragma unroll
        for (int a = 0; a < 3; a++)
#pragma unroll
            for (int g = 0; g < 2; g++)
#pragma unroll
                for (int j = 0; j < 4; j++) acc[a][g][j] = 0.f;

        // prologue: stage chunk 0, prefetch chunk 1 (pure copies, no cvt)
        float4 rh0 = __ldcg((const float4*)(g_htf  + b0s * HH + kq0));
        float4 rh1 = __ldcg((const float4*)(g_htf  + b1s * HH + kq1));
        float4 rc0 = __ldcg((const float4*)(ctf_in + b0s * HH + kq0));
        float4 rc1 = __ldcg((const float4*)(ctf_in + b1s * HH + kq1));
        *(float4*)(sBh + b0s * 68 + kq0) = rh0;
        *(float4*)(sBh + b1s * 68 + kq1) = rh1;
        *(float4*)(sBc + b0s * 68 + kq0) = rc0;
        *(float4*)(sBc + b1s * 68 + kq1) = rc1;
        rh0 = __ldcg((const float4*)(g_htf  + b0s * HH + 64 + kq0));
        rh1 = __ldcg((const float4*)(g_htf  + b1s * HH + 64 + kq1));
        rc0 = __ldcg((const float4*)(ctf_in + b0s * HH + 64 + kq0));
        rc1 = __ldcg((const float4*)(ctf_in + b1s * HH + 64 + kq1));
        __syncthreads();

        for (int j = 0; j < 16; j++) {
            float* bh = sBh + (j & 1) * 2176;
            float* bc = sBc + (j & 1) * 2176;
            if (j < 15) {
                float* bhn = sBh + ((j + 1) & 1) * 2176;
                float* bcn = sBc + ((j + 1) & 1) * 2176;
                *(float4*)(bhn + b0s * 68 + kq0) = rh0;
                *(float4*)(bhn + b1s * 68 + kq1) = rh1;
                *(float4*)(bcn + b0s * 68 + kq0) = rc0;
                *(float4*)(bcn + b1s * 68 + kq1) = rc1;
                if (j < 14) {
                    int k2 = (j + 2) * 64;
                    rh0 = __ldcg((const float4*)(g_htf  + b0s * HH + k2 + kq0));
                    rh1 = __ldcg((const float4*)(g_htf  + b1s * HH + k2 + kq1));
                    rc0 = __ldcg((const float4*)(ctf_in + b0s * HH + k2 + kq0));
                    rc1 = __ldcg((const float4*)(ctf_in + b1s * HH + k2 + kq1));
                }
            }
#pragma unroll
            for (int q = 0; q < 2; q++) {
                const int kt = kw * 2 + q, colo = kt * 8;
                unsigned h0a = *(const unsigned*)(bh + brow0 + colo);
                unsigned h1a = *(const unsigned*)(bh + brow0 + colo + 4);
                unsigned h0b = *(const unsigned*)(bh + brow1 + colo);
                unsigned h1b = *(const unsigned*)(bh + brow1 + colo + 4);
                unsigned c0a = *(const unsigned*)(bc + brow0 + colo);
                unsigned c1a = *(const unsigned*)(bc + brow0 + colo + 4);
                unsigned c0b = *(const unsigned*)(bc + brow1 + colo);
                unsigned c1b = *(const unsigned*)(bc + brow1 + colo + 4);
                const int gkt = j * 8 + kt;
                uint4 a0 = *(const uint4*)(sW + gkt * 128 + lane * 4);
                uint4 a1 = *(const uint4*)(sW + 16384 + gkt * 128 + lane * 4);
                uint4 a2 = *(const uint4*)(sW + 32768 + gkt * 128 + lane * 4);
                mma_tf32(acc[0][0], a0, h0a, h1a);
                mma_tf32(acc[0][1], a0, h0b, h1b);
                mma_tf32(acc[1][0], a1, h0a, h1a);
                mma_tf32(acc[1][1], a1, h0b, h1b);
                mma_tf32(acc[2][0], a2, c0a, c1a);
                mma_tf32(acc[2][1], a2, c0b, c1b);
            }
            __syncthreads();
        }

        // cross-k-split reduction; warps 0,1 (kw==0) hold totals
        if (kw > 0) {
            float* dst = sB + (((kw - 1) * 2 + bgset) * 32 + lane) * 24;
#pragma unroll
            for (int a = 0; a < 3; a++)
#pragma unroll
                for (int g = 0; g < 2; g++)
#pragma unroll
                    for (int j = 0; j < 4; j++) dst[a * 8 + g * 4 + j] = acc[a][g][j];
        }
        __syncthreads();
        if (kw == 0) {
#pragma unroll
            for (int r = 0; r < 3; r++) {
                const float* sp = sB + ((r * 2 + bgset) * 32 + lane) * 24;
#pragma unroll
                for (int a = 0; a < 3; a++)
#pragma unroll
                    for (int g = 0; g < 2; g++)
#pragma unroll
                        for (int j = 0; j < 4; j++) acc[a][g][j] += sp[a * 8 + g * 4 + j];
            }
            // local pointwise: gates, cy, po
#pragma unroll
            for (int gj = 0; gj < 4; gj++) {
                int g = gj >> 1, jb = gj & 1;
                float hi = acc[0][g][jb],     hf = acc[0][g][2 + jb];
                float hc = acc[1][g][jb],     ho = acc[1][g][2 + jb];
                float ci = acc[2][g][jb],     cf = acc[2][g][2 + jb];
                float pi = pP[0][gj] + hi + ci;
                float pf = pP[1][gj] + hf + cf;
                float pg = pP[2][gj] + hc;
                float po = pP[3][gj] + ho;
                float iv = 1.f / (1.f + expf(-pi));
                float fv = 1.f / (1.f + expf(-pf));
                float gv = tanhf(pg);
                float cy = fmaf(fv, pC[gj], iv * gv);
                g_c[nxt][offs[gj]] = cy;
                g_ctf[nxt][offs[gj]] = __uint_as_float(cvt_tf32(cy));
                g_po[offs[gj]] = po;
            }
        }
        // barrier B (cy/po published)
        bar_arrive(g_fB, bId, (unsigned)(t + 1));
        if (bId == 0) bar_master(g_fB, 128, (unsigned)(t + 1), &g_genB);
        else          bar_spin(&g_genB, (unsigned)(t + 1));

        // ---------- phase 2: o = sig(po + cy@Wcyo^T), h ----------
        {
            const float* cyp  = g_c[nxt];
            const float* cytf = g_ctf[nxt];
            const float* cyb  = cytf + (size_t)(half * 16 + crow) * HH;

            // epilogue operand prefetch (warp 0)
            float ppo[2][4], pcy[2][4];
            if (w == 0) {
#pragma unroll
                for (int g = 0; g < 2; g++)
#pragma unroll
                    for (int j = 0; j < 4; j++) {
                        int row = ng * 16 + (lane >> 2) + 8 * (j >> 1);
                        int bcol = half * 16 + g * 8 + 2 * (lane & 3) + (j & 1);
                        int off = bcol * HH + row;
                        ppo[g][j] = __ldcg(&g_po[off]);
                        pcy[g][j] = __ldcg(&cyp[off]);
                    }
            }

            float acc2[2][4];
#pragma unroll
            for (int g = 0; g < 2; g++)
#pragma unroll
                for (int j = 0; j < 4; j++) acc2[g][j] = 0.f;

            // prologue: stage chunk 0, prefetch cy chunk 1; A-frags in regs
            float4 ry = __ldcg((const float4*)(cyb + cq));
            *(float4*)(sCy + crow * 68 + cq) = ry;
            ry = __ldcg((const float4*)(cyb + 64 + cq));
            uint4 aCur = __ldg((const uint4*)(wsrc2 + (0 * 8 + w) * 128) + lane);
            uint4 aNxt = __ldg((const uint4*)(wsrc2 + (1 * 8 + w) * 128) + lane);
            uint4 aN2  = __ldg((const uint4*)(wsrc2 + (2 * 8 + w) * 128) + lane);
            const int colo2 = w * 8;
            __syncthreads();

            for (int j = 0; j < 16; j++) {
                float* cb = sCy + (j & 1) * 1088;
                if (j < 15) {
                    *(float4*)(sCy + ((j + 1) & 1) * 1088 + crow * 68 + cq) = ry;
                    if (j < 14)
                        ry = __ldcg((const float4*)(cyb + (j + 2) * 64 + cq));
                }
                unsigned y0a = *(const unsigned*)(cb + prow0 + colo2);
                unsigned y1a = *(const unsigned*)(cb + prow0 + colo2 + 4);
                unsigned y0b = *(const unsigned*)(cb + prow1 + colo2);
                unsigned y1b = *(const unsigned*)(cb + prow1 + colo2 + 4);
                mma_tf32(acc2[0], aCur, y0a, y1a);
                mma_tf32(acc2[1], aCur, y0b, y1b);
                aCur = aNxt; aNxt = aN2;
                if (j < 13)
                    aN2 = __ldg((const uint4*)(wsrc2 + ((j + 3) * 8 + w) * 128) + lane);
                __syncthreads();
            }

            // reduce over 8 k-split warps
            if (w > 0) {
                float* dst = sRedW + ((w - 1) * 32 + lane) * 8;
#pragma unroll
                for (int g = 0; g < 2; g++)
#pragma unroll
                    for (int j = 0; j < 4; j++) dst[g * 4 + j] = acc2[g][j];
            }
            __syncthreads();
            if (w == 0) {
#pragma unroll
                for (int r = 0; r < 7; r++) {
                    const float* sp = sRedW + (r * 32 + lane) * 8;
#pragma unroll
                    for (int g = 0; g < 2; g++)
#pragma unroll
                        for (int j = 0; j < 4; j++) acc2[g][j] += sp[g * 4 + j];
                }
#pragma unroll
                for (int g = 0; g < 2; g++)
#pragma unroll
                    for (int j = 0; j < 4; j++) {
                        int row = ng * 16 + (lane >> 2) + 8 * (j >> 1);
                        int bcol = half * 16 + g * 8 + 2 * (lane & 3) + (j & 1);
                        int off = bcol * HH + row;
                        float o = 1.f / (1.f + expf(-(ppo[g][j] + acc2[g][j])));
                        float hy = o * tanhf(pcy[g][j]);
                        g_htf[off] = __uint_as_float(cvt_tf32(hy));
                        out[(size_t)t * BH + off] = hy;
                    }
            }
        }
        // barrier C (h published)
        bar_arrive(g_fC, bId, (unsigned)(t + 1));
        if (bId == 0) bar_master(g_fC, 128, (unsigned)(t + 1), &g_genC);
        else          bar_spin(&g_genC, (unsigned)(t + 1));
    }
}

extern "C" void kernel_launch(void* const* d_in, const int* in_sizes, int n_in,
                              void* d_out, int out_size)
{
    const float* X     = (const float*)d_in[0];
    const float* h0    = (const float*)d_in[1];
    const float* c0    = (const float*)d_in[2];
    const float* w_ii  = (const float*)d_in[3];
    const float* w_hi  = (const float*)d_in[4];
    const float* w_ci  = (const float*)d_in[5];
    const float* w_if  = (const float*)d_in[6];
    const float* w_hf  = (const float*)d_in[7];
    const float* w_cf  = (const float*)d_in[8];
    const float* w_ic  = (const float*)d_in[9];
    const float* w_hc  = (const float*)d_in[10];
    const float* w_io  = (const float*)d_in[11];
    const float* w_ho  = (const float*)d_in[12];
    const float* w_cyo = (const float*)d_in[13];
    float* out = (float*)d_out;

    cudaFuncSetAttribute(lstm_kernel,
                         cudaFuncAttributeMaxDynamicSharedMemorySize,
                         SMEM_FLOATS * 4);
    cudaFuncSetAttribute(proj2_kernel,
                         cudaFuncAttributeMaxDynamicSharedMemorySize,
                         PROJ_SMEM * 4);

    init_kernel<<<128, 256>>>(h0, c0,
        (const float*)d_in[14], (const float*)d_in[15], (const float*)d_in[16],
        (const float*)d_in[17], (const float*)d_in[18], (const float*)d_in[19],
        (const float*)d_in[20], (const float*)d_in[21], (const float*)d_in[22],
        (const float*)d_in[23], (const float*)d_in[24]);
    pack_kernel<<<28672, 256>>>(w_hi, w_hf, w_hc, w_ho, w_ci, w_cf, w_cyo);
    pack_in_kernel<<<8192, 256>>>(w_ii, w_if, w_ic, w_io);
    proj2_kernel<<<128, 256, PROJ_SMEM * 4>>>(X);
    lstm_kernel<<<NBLK, 256, SMEM_FLOATS * 4>>>(out);
}